// round 15
// baseline (speedup 1.0000x reference)
#include <cuda_runtime.h>
#include <cstddef>

// Inputs (metadata order):
//  0: transformation  float32  (4,4)
//  1: src_points      float32  (N,4)
//  2: tar_points      float32  (N,4)
//  3: covs_src        float32  (N,4,4)
//  4: covs_tar        float32  (N,4,4)
//  5: nearest_indices int32    (N,)
// Output: scalar float = 0.5 * mean(maha)
//
// HBM-bound gather+reduce. Base = R13 winner (tpb=512, 4 CTAs/SM, 32 regs =
// exact RF fit, 68.2us @ 83.2% DRAM). This round: 64B cov records loaded as
// 2x 256-bit ld.global.nc.v4.b64 instead of 3x 16B -> per-point L1tex
// requests drop 9 -> 7 with identical DRAM sector traffic (row 3 shares the
// second 32B sector with row 2). launch_bounds(512,4) pins the 32-reg
// occupancy cliff.

__device__ __forceinline__ float2 u64_as_f2(unsigned long long v) {
    float2 r;
    r.x = __uint_as_float((unsigned)(v & 0xffffffffull));
    r.y = __uint_as_float((unsigned)(v >> 32));
    return r;
}

// 32-byte (256-bit) read-only load. p must be 32B aligned.
__device__ __forceinline__ void ldg256(const float* p, float4& lo, float4& hi) {
    unsigned long long r0, r1, r2, r3;
    asm("ld.global.nc.v4.b64 {%0,%1,%2,%3}, [%4];"
        : "=l"(r0), "=l"(r1), "=l"(r2), "=l"(r3) : "l"(p));
    const float2 a = u64_as_f2(r0), b = u64_as_f2(r1);
    const float2 c = u64_as_f2(r2), d = u64_as_f2(r3);
    lo = make_float4(a.x, a.y, b.x, b.y);
    hi = make_float4(c.x, c.y, d.x, d.y);
}

__global__ void gicp_zero_out(float* out) {
    if (blockIdx.x == 0 && threadIdx.x == 0) out[0] = 0.0f;
}

__global__ __launch_bounds__(512, 4) void gicp_kernel(
    const float*  __restrict__ T,         // 16 floats
    const float4* __restrict__ src,       // N rows (x,y,z,1)
    const float4* __restrict__ tar,       // N rows
    const float*  __restrict__ covs_src,  // N * 16 floats
    const float*  __restrict__ covs_tar,  // N * 16 floats
    const int*    __restrict__ idx,       // N
    float*        __restrict__ out,
    int n, float scale)
{
    const int i = blockIdx.x * blockDim.x + threadIdx.x;
    float acc = 0.0f;

    if (i < n) {
        // Broadcast load of the 4x4 transformation (L1 hit after warmup).
        float t[16];
        #pragma unroll
        for (int k = 0; k < 16; ++k) t[k] = __ldg(T + k);

        const int j = __ldg(idx + i);

        // Issue all memory traffic up front for MLP.
        const float4 s = __ldg(src + (size_t)i);
        float4 c0, c1, c2, c3u;
        ldg256(covs_src + (size_t)i * 16,     c0, c1);
        ldg256(covs_src + (size_t)i * 16 + 8, c2, c3u);
        const float4 tp = __ldg(tar + (size_t)j);
        float4 d0, d1, d2, d3u;
        ldg256(covs_tar + (size_t)j * 16,     d0, d1);
        ldg256(covs_tar + (size_t)j * 16 + 8, d2, d3u);
        (void)c3u; (void)d3u;

        // transformed_src = src_row_vector @ T  (take xyz)
        const float tsx = s.x * t[0] + s.y * t[4] + s.z * t[8]  + s.w * t[12];
        const float tsy = s.x * t[1] + s.y * t[5] + s.z * t[9]  + s.w * t[13];
        const float tsz = s.x * t[2] + s.y * t[6] + s.z * t[10] + s.w * t[14];

        const float rx = tp.x - tsx;
        const float ry = tp.y - tsy;
        const float rz = tp.z - tsz;

        // B = R * C3 ; M = Ctar3 + B * R^T (symmetric), R[a][k] = t[4a+k]
        const float C00 = c0.x, C01 = c0.y, C02 = c0.z;
        const float C10 = c1.x, C11 = c1.y, C12 = c1.z;
        const float C20 = c2.x, C21 = c2.y, C22 = c2.z;

        float B[3][3];
        #pragma unroll
        for (int a = 0; a < 3; ++a) {
            const float r0 = t[4 * a + 0], r1 = t[4 * a + 1], r2 = t[4 * a + 2];
            B[a][0] = r0 * C00 + r1 * C10 + r2 * C20;
            B[a][1] = r0 * C01 + r1 * C11 + r2 * C21;
            B[a][2] = r0 * C02 + r1 * C12 + r2 * C22;
        }

        // Symmetric M = [a b c; b d e; c e f]
        const float ma = B[0][0] * t[0] + B[0][1] * t[1] + B[0][2] * t[2]  + d0.x;
        const float mb = B[0][0] * t[4] + B[0][1] * t[5] + B[0][2] * t[6]  + d0.y;
        const float mc = B[0][0] * t[8] + B[0][1] * t[9] + B[0][2] * t[10] + d0.z;
        const float md = B[1][0] * t[4] + B[1][1] * t[5] + B[1][2] * t[6]  + d1.y;
        const float me = B[1][0] * t[8] + B[1][1] * t[9] + B[1][2] * t[10] + d1.z;
        const float mf = B[2][0] * t[8] + B[2][1] * t[9] + B[2][2] * t[10] + d2.z;

        // maha = res^T adj(M) res / det(M)
        const float adj00 = md * mf - me * me;
        const float adj01 = mc * me - mb * mf;
        const float adj02 = mb * me - mc * md;
        const float det   = ma * adj00 + mb * adj01 + mc * adj02;
        const float adj11 = ma * mf - mc * mc;
        const float adj12 = mb * mc - ma * me;
        const float adj22 = ma * md - mb * mb;

        const float q =
            rx * (rx * adj00 + ry * adj01 + rz * adj02) +
            ry * (rx * adj01 + ry * adj11 + rz * adj12) +
            rz * (rx * adj02 + ry * adj12 + rz * adj22);

        acc = (q / det) * scale;   // scale = 0.5 / N folded in
    }

    // Warp reduce
    #pragma unroll
    for (int o = 16; o > 0; o >>= 1)
        acc += __shfl_down_sync(0xffffffffu, acc, o);

    __shared__ float ws[16];
    if ((threadIdx.x & 31) == 0) ws[threadIdx.x >> 5] = acc;
    __syncthreads();

    if (threadIdx.x < 16) {
        float v = ws[threadIdx.x];
        #pragma unroll
        for (int o = 8; o > 0; o >>= 1)
            v += __shfl_down_sync(0xffffu, v, o);
        if (threadIdx.x == 0) atomicAdd(out, v);
    }
}

extern "C" void kernel_launch(void* const* d_in, const int* in_sizes, int n_in,
                              void* d_out, int out_size)
{
    const float*  T        = (const float*) d_in[0];
    const float4* src      = (const float4*)d_in[1];
    const float4* tar      = (const float4*)d_in[2];
    const float*  covs_src = (const float*) d_in[3];
    const float*  covs_tar = (const float*) d_in[4];
    const int*    idx      = (const int*)   d_in[5];
    float* out = (float*)d_out;

    const int n = in_sizes[5];          // N points
    const float scale = 0.5f / (float)n;

    gicp_zero_out<<<1, 32>>>(out);

    const int tpb = 512;
    const int grid = (n + tpb - 1) / tpb;
    gicp_kernel<<<grid, tpb>>>(T, src, tar, covs_src, covs_tar, idx, out, n, scale);
}

// round 16
// speedup vs baseline: 1.0249x; 1.0249x over previous
#include <cuda_runtime.h>
#include <cstddef>

// Inputs (metadata order):
//  0: transformation  float32  (4,4)
//  1: src_points      float32  (N,4)
//  2: tar_points      float32  (N,4)
//  3: covs_src        float32  (N,4,4)
//  4: covs_tar        float32  (N,4,4)
//  5: nearest_indices int32    (N,)
// Output: scalar float = 0.5 * mean(maha)
//
// FINAL: HBM-bound gather+reduce at the measured roofline: 68.2us,
// 83.2% DRAM (6592 GB/s) over ~449MB effective traffic.
// Measured-out alternatives: L2 eviction hints (inert; reuse set > L2),
// target partitioning / index binning (sell i-locality or MLP), 2pt/thread
// and persistent grids (trade away occupancy), 256-bit loads (serialize
// request halves), tpb 256/1024 (CTA-boundary drain vs retire granularity).
// Winning shape: tpb=512 (4 CTAs/SM, 32 regs = exact RF fit), nine
// independent 16B __ldg per point issued before compute, and
// res^T adj(M) res / det(M) instead of forming the 3x3 inverse
// (M is SPD, min eigenvalue >= 0.1 -> well conditioned).

__global__ void gicp_zero_out(float* out) {
    if (blockIdx.x == 0 && threadIdx.x == 0) out[0] = 0.0f;
}

__global__ __launch_bounds__(512) void gicp_kernel(
    const float*  __restrict__ T,         // 16 floats
    const float4* __restrict__ src,       // N rows (x,y,z,1)
    const float4* __restrict__ tar,       // N rows
    const float4* __restrict__ covs_src,  // N * 4 rows
    const float4* __restrict__ covs_tar,  // N * 4 rows
    const int*    __restrict__ idx,       // N
    float*        __restrict__ out,
    int n, float scale)
{
    const int i = blockIdx.x * blockDim.x + threadIdx.x;
    float acc = 0.0f;

    if (i < n) {
        // Broadcast load of the 4x4 transformation (L1 hit after warmup).
        float t[16];
        #pragma unroll
        for (int k = 0; k < 16; ++k) t[k] = __ldg(T + k);

        const int j = __ldg(idx + i);

        // Issue all memory traffic up front for MLP.
        const float4 s  = __ldg(src + (size_t)i);
        const float4 c0 = __ldg(covs_src + 4 * (size_t)i + 0);
        const float4 c1 = __ldg(covs_src + 4 * (size_t)i + 1);
        const float4 c2 = __ldg(covs_src + 4 * (size_t)i + 2);
        const float4 tp = __ldg(tar + (size_t)j);
        const float4 d0 = __ldg(covs_tar + 4 * (size_t)j + 0);
        const float4 d1 = __ldg(covs_tar + 4 * (size_t)j + 1);
        const float4 d2 = __ldg(covs_tar + 4 * (size_t)j + 2);

        // transformed_src = src_row_vector @ T  (take xyz)
        const float tsx = s.x * t[0] + s.y * t[4] + s.z * t[8]  + s.w * t[12];
        const float tsy = s.x * t[1] + s.y * t[5] + s.z * t[9]  + s.w * t[13];
        const float tsz = s.x * t[2] + s.y * t[6] + s.z * t[10] + s.w * t[14];

        const float rx = tp.x - tsx;
        const float ry = tp.y - tsy;
        const float rz = tp.z - tsz;

        // B = R * C3 ; M = Ctar3 + B * R^T (symmetric), R[a][k] = t[4a+k]
        const float C00 = c0.x, C01 = c0.y, C02 = c0.z;
        const float C10 = c1.x, C11 = c1.y, C12 = c1.z;
        const float C20 = c2.x, C21 = c2.y, C22 = c2.z;

        float B[3][3];
        #pragma unroll
        for (int a = 0; a < 3; ++a) {
            const float r0 = t[4 * a + 0], r1 = t[4 * a + 1], r2 = t[4 * a + 2];
            B[a][0] = r0 * C00 + r1 * C10 + r2 * C20;
            B[a][1] = r0 * C01 + r1 * C11 + r2 * C21;
            B[a][2] = r0 * C02 + r1 * C12 + r2 * C22;
        }

        // Symmetric M = [a b c; b d e; c e f]
        const float ma = B[0][0] * t[0] + B[0][1] * t[1] + B[0][2] * t[2]  + d0.x;
        const float mb = B[0][0] * t[4] + B[0][1] * t[5] + B[0][2] * t[6]  + d0.y;
        const float mc = B[0][0] * t[8] + B[0][1] * t[9] + B[0][2] * t[10] + d0.z;
        const float md = B[1][0] * t[4] + B[1][1] * t[5] + B[1][2] * t[6]  + d1.y;
        const float me = B[1][0] * t[8] + B[1][1] * t[9] + B[1][2] * t[10] + d1.z;
        const float mf = B[2][0] * t[8] + B[2][1] * t[9] + B[2][2] * t[10] + d2.z;

        // maha = res^T adj(M) res / det(M)
        const float adj00 = md * mf - me * me;
        const float adj01 = mc * me - mb * mf;
        const float adj02 = mb * me - mc * md;
        const float det   = ma * adj00 + mb * adj01 + mc * adj02;
        const float adj11 = ma * mf - mc * mc;
        const float adj12 = mb * mc - ma * me;
        const float adj22 = ma * md - mb * mb;

        const float q =
            rx * (rx * adj00 + ry * adj01 + rz * adj02) +
            ry * (rx * adj01 + ry * adj11 + rz * adj12) +
            rz * (rx * adj02 + ry * adj12 + rz * adj22);

        acc = (q / det) * scale;   // scale = 0.5 / N folded in
    }

    // Warp reduce
    #pragma unroll
    for (int o = 16; o > 0; o >>= 1)
        acc += __shfl_down_sync(0xffffffffu, acc, o);

    __shared__ float ws[16];
    if ((threadIdx.x & 31) == 0) ws[threadIdx.x >> 5] = acc;
    __syncthreads();

    if (threadIdx.x < 16) {
        float v = ws[threadIdx.x];
        #pragma unroll
        for (int o = 8; o > 0; o >>= 1)
            v += __shfl_down_sync(0xffffu, v, o);
        if (threadIdx.x == 0) atomicAdd(out, v);
    }
}

extern "C" void kernel_launch(void* const* d_in, const int* in_sizes, int n_in,
                              void* d_out, int out_size)
{
    const float*  T        = (const float*) d_in[0];
    const float4* src      = (const float4*)d_in[1];
    const float4* tar      = (const float4*)d_in[2];
    const float4* covs_src = (const float4*)d_in[3];
    const float4* covs_tar = (const float4*)d_in[4];
    const int*    idx      = (const int*)   d_in[5];
    float* out = (float*)d_out;

    const int n = in_sizes[5];          // N points
    const float scale = 0.5f / (float)n;

    gicp_zero_out<<<1, 32>>>(out);

    const int tpb = 512;
    const int grid = (n + tpb - 1) / tpb;
    gicp_kernel<<<grid, tpb>>>(T, src, tar, covs_src, covs_tar, idx, out, n, scale);
}